// round 10
// baseline (speedup 1.0000x reference)
#include <cuda_runtime.h>
#include <math.h>
#include <stdint.h>

#define NF 26
#define ND 16
#define H1 256
#define H2 128
#define ROWS 64
#define K1 (NF*ND)     // 416
#define EPSF 1e-5f
#define NT 512

// float offsets in dynamic smem
#define OFF_AF    0            // GEMM1 A frags: 52*4*32*4 = 26624 fl; reused for A2 frags (16384 fl)
#define OFF_WB0   26624        // 8192 fl (32KB) B-frag staging buffer 0
#define OFF_WB1   34816        // 8192 fl buffer 1
#define OFF_FM    43008
#define OFF_LOGIT (OFF_FM + 64)
#define OFF_S1    (OFF_LOGIT + 64)
#define OFF_B1    (OFF_S1 + 256)
#define OFF_S2    (OFF_B1 + 256)
#define OFF_B2    (OFF_S2 + 128)
#define OFF_W3    (OFF_B2 + 128)
#define SMEM_FLOATS (OFF_W3 + 128)   // 44032 -> 176128 B

__device__ __forceinline__ uint32_t smem_u32(const void* p){
    uint32_t a;
    asm("{ .reg .u64 t; cvta.to.shared.u64 t, %1; cvt.u32.u64 %0, t; }" : "=r"(a) : "l"(p));
    return a;
}
__device__ __forceinline__ uint32_t f2tf(float x){
    uint32_t r; asm("cvt.rna.tf32.f32 %0, %1;" : "=r"(r) : "f"(x)); return r;
}
__device__ __forceinline__ void mma_tf32(float* d, const uint32_t* a, const uint32_t* b){
    asm volatile("mma.sync.aligned.m16n8k8.row.col.f32.tf32.tf32.f32 "
        "{%0,%1,%2,%3}, {%4,%5,%6,%7}, {%8,%9}, {%0,%1,%2,%3};"
        : "+f"(d[0]), "+f"(d[1]), "+f"(d[2]), "+f"(d[3])
        : "r"(a[0]), "r"(a[1]), "r"(a[2]), "r"(a[3]), "r"(b[0]), "r"(b[1]));
}
__device__ __forceinline__ void lds4u(uint32_t* r, uint32_t addr){
    asm volatile("ld.shared.v4.b32 {%0,%1,%2,%3}, [%4];"
                 : "=r"(r[0]), "=r"(r[1]), "=r"(r[2]), "=r"(r[3]) : "r"(addr));
}
__device__ __forceinline__ void lds2u(uint32_t* r, uint32_t addr){
    asm volatile("ld.shared.v2.b32 {%0,%1}, [%2];" : "=r"(r[0]), "=r"(r[1]) : "r"(addr));
}
__device__ __forceinline__ void sts1u(uint32_t addr, uint32_t v){
    asm volatile("st.shared.b32 [%0], %1;" :: "r"(addr), "r"(v));
}

__global__ __launch_bounds__(NT, 1)
void deepfm_mma2(const int* __restrict__ X, const float* __restrict__ emb1,
                 const float* __restrict__ emb2,
                 const float* __restrict__ W1, const float* __restrict__ b1,
                 const float* __restrict__ g1, const float* __restrict__ be1,
                 const float* __restrict__ m1, const float* __restrict__ v1,
                 const float* __restrict__ W2, const float* __restrict__ b2,
                 const float* __restrict__ g2, const float* __restrict__ be2,
                 const float* __restrict__ m2, const float* __restrict__ v2,
                 const float* __restrict__ W3, const float* __restrict__ b3,
                 float* __restrict__ out, int Btot, int V)
{
    extern __shared__ float sm[];
    float* fm_s    = sm + OFF_FM;
    float* logit_s = sm + OFF_LOGIT;
    float* S1f     = sm + OFF_S1;
    float* B1f     = sm + OFF_B1;
    float* S2f     = sm + OFF_S2;
    float* B2f     = sm + OFF_B2;
    float* W3s     = sm + OFF_W3;

    const int tid  = threadIdx.x;
    const int wid  = tid >> 5;
    const int lane = tid & 31;
    const int b0   = blockIdx.x * ROWS;
    const uint32_t smbase = smem_u32(sm);

    if (tid < 64) logit_s[tid] = 0.f;
    if (tid < 256) {
        float s = g1[tid] * rsqrtf(v1[tid] + EPSF);
        S1f[tid] = s; B1f[tid] = be1[tid] + (b1[tid] - m1[tid]) * s;
        if (tid < 128) {
            float s2 = g2[tid] * rsqrtf(v2[tid] + EPSF);
            S2f[tid] = s2; B2f[tid] = be2[tid] + (b2[tid] - m2[tid]) * s2;
            W3s[tid] = W3[tid];
        }
    }

    // ---- Phase 1: gather e2 -> A fragments (tf32), FM sums in registers ----
    {
        const int r  = tid >> 3;        // 0..63
        const int fi = tid & 7;
        const int mt = r >> 4;
        float s[ND], q[ND]; float fm1 = 0.f;
        #pragma unroll
        for (int d = 0; d < ND; d++) { s[d] = 0.f; q[d] = 0.f; }
        const int* xr = X + (size_t)(b0 + r) * NF;
        #pragma unroll
        for (int j = 0; j < 4; j++) {
            int f = fi + 8*j;
            if (f < NF) {
                int idx = xr[f];
                fm1 += emb1[(size_t)f * V + idx];
                const float4* e = (const float4*)(emb2 + ((size_t)f * V + idx) * ND);
                #pragma unroll
                for (int qq = 0; qq < 4; qq++) {
                    float4 v4 = e[qq];
                    float vv[4] = {v4.x, v4.y, v4.z, v4.w};
                    #pragma unroll
                    for (int b = 0; b < 4; b++) {
                        int d = 4*qq + b;
                        float v = vv[b];
                        s[d] += v; q[d] += v*v;
                        int kstep = f*2 + (d >> 3);
                        int kcol  = d & 7;
                        int ln    = (r & 7)*4 + (kcol & 3);
                        int slot  = ((r >> 3) & 1) | ((kcol >> 2) << 1);
                        uint32_t fidx = ((uint32_t)(kstep*4 + mt)*32u + (uint32_t)ln)*4u + (uint32_t)slot;
                        sts1u(smbase + (OFF_AF + fidx)*4u, f2tf(v));
                    }
                }
            }
        }
        // reduce over the 8 fi-threads of this row (lanes differing in bits 0..2)
        #pragma unroll
        for (int m = 1; m < 8; m <<= 1) {
            fm1 += __shfl_xor_sync(0xffffffffu, fm1, m);
            #pragma unroll
            for (int d = 0; d < ND; d++) {
                s[d] += __shfl_xor_sync(0xffffffffu, s[d], m);
                q[d] += __shfl_xor_sync(0xffffffffu, q[d], m);
            }
        }
        if (fi == 0) {
            float fm2 = 0.f;
            #pragma unroll
            for (int d = 0; d < ND; d++) fm2 += 0.5f*(s[d]*s[d] - q[d]);
            fm_s[r] = fm1 + fm2;
        }
    }

    const float4* W1g = (const float4*)W1;   // [416][64 float4]
    const float4* W2g = (const float4*)W2;   // [256][32 float4]

    // ---- stage W1 chunk 0 into B-frag buffer 0 ----
    {
        #pragma unroll
        for (int i = 0; i < 4; i++) {
            int t = tid + i*NT;                 // < 2048
            int kk = t >> 6, c4 = t & 63;
            float4 w = W1g[(size_t)kk * 64 + c4];
            float wv[4] = {w.x, w.y, w.z, w.w};
            #pragma unroll
            for (int b = 0; b < 4; b++) {
                int n = c4*4 + b;
                int kstep = kk >> 3, kcol = kk & 7;
                uint32_t fidx = ((uint32_t)(kstep*32 + (n >> 3))*32u
                               + (uint32_t)((n & 7)*4 + (kcol & 3)))*2u + (uint32_t)(kcol >> 2);
                sts1u(smbase + (OFF_WB0 + fidx)*4u, f2tf(wv[b]));
            }
        }
    }
    __syncthreads();

    // ---- GEMM1: 13 chunks of 32k (4 k-steps), warp = m16 x n64 ----
    const int wm = wid & 3, wn = wid >> 2;
    float acc[32];
    #pragma unroll
    for (int i = 0; i < 32; i++) acc[i] = 0.f;
    {
        float4 pf[4];
        #pragma unroll 1
        for (int c = 0; c < 13; c++) {
            if (c + 1 < 13) {
                #pragma unroll
                for (int i = 0; i < 4; i++) {
                    int t = tid + i*NT;
                    pf[i] = W1g[(size_t)((c+1)*32 + (t >> 6)) * 64 + (t & 63)];
                }
            }
            uint32_t bufb = smbase + (uint32_t)((c & 1) ? OFF_WB1 : OFF_WB0)*4u;
            #pragma unroll
            for (int ks = 0; ks < 4; ks++) {
                int ksg = c*4 + ks;
                uint32_t a[4];
                lds4u(a, smbase + (uint32_t)(OFF_AF)*4u + ((uint32_t)(ksg*4 + wm)*32u + (uint32_t)lane)*16u);
                #pragma unroll
                for (int nf = 0; nf < 8; nf++) {
                    uint32_t b[2];
                    lds2u(b, bufb + ((uint32_t)(ks*32 + wn*8 + nf)*32u + (uint32_t)lane)*8u);
                    mma_tf32(&acc[nf*4], a, b);
                }
            }
            if (c + 1 < 13) {
                uint32_t dstb = smbase + (uint32_t)((c & 1) ? OFF_WB0 : OFF_WB1)*4u;
                #pragma unroll
                for (int i = 0; i < 4; i++) {
                    int t = tid + i*NT;
                    int kk = t >> 6, c4 = t & 63;
                    float wv[4] = {pf[i].x, pf[i].y, pf[i].z, pf[i].w};
                    #pragma unroll
                    for (int b = 0; b < 4; b++) {
                        int n = c4*4 + b;
                        int kstep = kk >> 3, kcol = kk & 7;
                        uint32_t fidx = ((uint32_t)(kstep*32 + (n >> 3))*32u
                                       + (uint32_t)((n & 7)*4 + (kcol & 3)))*2u + (uint32_t)(kcol >> 2);
                        sts1u(dstb + fidx*4u, f2tf(wv[b]));
                    }
                }
            }
            __syncthreads();
        }
    }

    // ---- BN1 + ReLU on D frags -> A2 frags (overwrite OFF_AF); stage W2 chunk 0 ----
    {
        float4 pf[4];
        #pragma unroll
        for (int i = 0; i < 4; i++) {
            int t = tid + i*NT;                 // < 2048
            pf[i] = W2g[(size_t)(t >> 5) * 32 + (t & 31)];
        }
        const int r0 = wm*16 + (lane >> 2);
        #pragma unroll
        for (int nf = 0; nf < 8; nf++) {
            int c0 = wn*64 + nf*8 + 2*(lane & 3);
            float Sa = S1f[c0],   Ba = B1f[c0];
            float Sb = S1f[c0+1], Bb = B1f[c0+1];
            float h00 = fmaxf(acc[nf*4+0]*Sa + Ba, 0.f);
            float h01 = fmaxf(acc[nf*4+1]*Sb + Bb, 0.f);
            float h10 = fmaxf(acc[nf*4+2]*Sa + Ba, 0.f);
            float h11 = fmaxf(acc[nf*4+3]*Sb + Bb, 0.f);
            int kstep2 = wn*8 + nf;
            uint32_t base = smbase + (uint32_t)OFF_AF*4u + (uint32_t)(kstep2*4 + wm)*512u;
            #pragma unroll
            for (int b = 0; b < 2; b++) {
                int kcol = 2*(lane & 3) + b;
                uint32_t ln = (uint32_t)((r0 & 7)*4 + (kcol & 3));
                uint32_t sl_lo = (uint32_t)(((r0 >> 3) & 1) | ((kcol >> 2) << 1));
                uint32_t sl_hi = sl_lo ^ 1u;     // r0+8 flips bit0 of slot
                sts1u(base + (ln*4u + sl_lo)*4u, f2tf(b ? h01 : h00));
                sts1u(base + (ln*4u + sl_hi)*4u, f2tf(b ? h11 : h10));
            }
        }
        #pragma unroll
        for (int i = 0; i < 4; i++) {
            int t = tid + i*NT;
            int kk = t >> 5, c4 = t & 31;
            float wv[4] = {pf[i].x, pf[i].y, pf[i].z, pf[i].w};
            #pragma unroll
            for (int b = 0; b < 4; b++) {
                int n = c4*4 + b;
                int kstep = kk >> 3, kcol = kk & 7;
                uint32_t fidx = ((uint32_t)(kstep*16 + (n >> 3))*32u
                               + (uint32_t)((n & 7)*4 + (kcol & 3)))*2u + (uint32_t)(kcol >> 2);
                sts1u(smbase + (uint32_t)(OFF_WB0)*4u + fidx*4u, f2tf(wv[b]));
            }
        }
    }
    __syncthreads();

    // ---- GEMM2: 4 chunks of 64k (8 k-steps), warp = m16 x n32 ----
    float acc2[16];
    #pragma unroll
    for (int i = 0; i < 16; i++) acc2[i] = 0.f;
    {
        float4 pf[4];
        #pragma unroll 1
        for (int c = 0; c < 4; c++) {
            if (c + 1 < 4) {
                #pragma unroll
                for (int i = 0; i < 4; i++) {
                    int t = tid + i*NT;
                    pf[i] = W2g[(size_t)((c+1)*64 + (t >> 5)) * 32 + (t & 31)];
                }
            }
            uint32_t bufb = smbase + (uint32_t)((c & 1) ? OFF_WB1 : OFF_WB0)*4u;
            #pragma unroll
            for (int ks = 0; ks < 8; ks++) {
                int ksg = c*8 + ks;
                uint32_t a[4];
                lds4u(a, smbase + (uint32_t)(OFF_AF)*4u + ((uint32_t)(ksg*4 + wm)*32u + (uint32_t)lane)*16u);
                #pragma unroll
                for (int nf = 0; nf < 4; nf++) {
                    uint32_t b[2];
                    lds2u(b, bufb + ((uint32_t)(ks*16 + wn*4 + nf)*32u + (uint32_t)lane)*8u);
                    mma_tf32(&acc2[nf*4], a, b);
                }
            }
            if (c + 1 < 4) {
                uint32_t dstb = smbase + (uint32_t)((c & 1) ? OFF_WB0 : OFF_WB1)*4u;
                #pragma unroll
                for (int i = 0; i < 4; i++) {
                    int t = tid + i*NT;
                    int kk = t >> 5, c4 = t & 31;
                    float wv[4] = {pf[i].x, pf[i].y, pf[i].z, pf[i].w};
                    #pragma unroll
                    for (int b = 0; b < 4; b++) {
                        int n = c4*4 + b;
                        int kstep = kk >> 3, kcol = kk & 7;
                        uint32_t fidx = ((uint32_t)(kstep*16 + (n >> 3))*32u
                                       + (uint32_t)((n & 7)*4 + (kcol & 3)))*2u + (uint32_t)(kcol >> 2);
                        sts1u(dstb + fidx*4u, f2tf(wv[b]));
                    }
                }
            }
            __syncthreads();
        }
    }

    // ---- BN2 + ReLU + W3 dot on D2 frags -> logits ----
    {
        const int r0 = wm*16 + (lane >> 2);
        float sum0 = 0.f, sum1 = 0.f;
        #pragma unroll
        for (int nf = 0; nf < 4; nf++) {
            int c0 = wn*32 + nf*8 + 2*(lane & 3);
            float Sa = S2f[c0],   Ba = B2f[c0],   wa = W3s[c0];
            float Sb = S2f[c0+1], Bb = B2f[c0+1], wb = W3s[c0+1];
            sum0 += fmaxf(acc2[nf*4+0]*Sa + Ba, 0.f)*wa + fmaxf(acc2[nf*4+1]*Sb + Bb, 0.f)*wb;
            sum1 += fmaxf(acc2[nf*4+2]*Sa + Ba, 0.f)*wa + fmaxf(acc2[nf*4+3]*Sb + Bb, 0.f)*wb;
        }
        atomicAdd(&logit_s[r0],     sum0);
        atomicAdd(&logit_s[r0 + 8], sum1);
    }
    __syncthreads();

    // ---- Epilogue ----
    if (tid < ROWS) {
        float x = logit_s[tid] + fm_s[tid] + b3[0];
        out[b0 + tid] = 1.f / (1.f + expf(-x));
    }
}

extern "C" void kernel_launch(void* const* d_in, const int* in_sizes, int n_in,
                              void* d_out, int out_size)
{
    const int*   X    = (const int*)  d_in[0];
    const float* emb1 = (const float*)d_in[1];
    const float* emb2 = (const float*)d_in[2];
    const float* W1   = (const float*)d_in[3];
    const float* b1   = (const float*)d_in[4];
    const float* g1   = (const float*)d_in[5];
    const float* be1  = (const float*)d_in[6];
    const float* m1   = (const float*)d_in[7];
    const float* v1   = (const float*)d_in[8];
    const float* W2   = (const float*)d_in[9];
    const float* b2   = (const float*)d_in[10];
    const float* g2   = (const float*)d_in[11];
    const float* be2  = (const float*)d_in[12];
    const float* m2   = (const float*)d_in[13];
    const float* v2   = (const float*)d_in[14];
    const float* W3   = (const float*)d_in[15];
    const float* b3   = (const float*)d_in[16];
    float* out = (float*)d_out;

    int B = in_sizes[0] / NF;
    int V = in_sizes[1] / NF;

    int smem = SMEM_FLOATS * (int)sizeof(float);   // 176128 B
    cudaFuncSetAttribute(deepfm_mma2, cudaFuncAttributeMaxDynamicSharedMemorySize, smem);
    deepfm_mma2<<<B/ROWS, NT, smem>>>(X, emb1, emb2, W1, b1, g1, be1, m1, v1,
                                      W2, b2, g2, be2, m2, v2, W3, b3,
                                      out, B, V);
}

// round 11
// speedup vs baseline: 2.8911x; 2.8911x over previous
#include <cuda_runtime.h>
#include <math.h>
#include <stdint.h>

#define NF 26
#define ND 16
#define H1 256
#define H2 128
#define ROWS 64
#define K1 (NF*ND)     // 416
#define EPSF 1e-5f
#define NT 512
#define STRA 68        // plain [k][row] row stride (floats): 68 % 32 = 4 -> bank spread
#define FRS 66         // B-frag stride (floats): 66 % 32 = 2 -> bank spread

// float offsets in dynamic smem
#define OFF_A     0                    // e2 [416][68] = 28288 fl; later h1 [256][68] = 17408 fl
#define OFF_WB0   28288                // 128 frags * 66 = 8448 fl
#define OFF_WB1   36736
#define OFF_FM    45184
#define OFF_LOGIT (OFF_FM + 64)
#define OFF_S1    (OFF_LOGIT + 64)
#define OFF_B1    (OFF_S1 + 256)
#define OFF_S2    (OFF_B1 + 256)
#define OFF_B2    (OFF_S2 + 128)
#define OFF_W3    (OFF_B2 + 128)
#define SMEM_FLOATS (OFF_W3 + 128)     // 46208 -> 184832 B

__device__ __forceinline__ uint32_t smem_u32(const void* p){
    uint32_t a;
    asm("{ .reg .u64 t; cvta.to.shared.u64 t, %1; cvt.u32.u64 %0, t; }" : "=r"(a) : "l"(p));
    return a;
}
__device__ __forceinline__ uint32_t f2tf(float x){
    uint32_t r; asm("cvt.rna.tf32.f32 %0, %1;" : "=r"(r) : "f"(x)); return r;
}
__device__ __forceinline__ void mma_tf32(float* d, const uint32_t* a, const uint32_t* b){
    asm volatile("mma.sync.aligned.m16n8k8.row.col.f32.tf32.tf32.f32 "
        "{%0,%1,%2,%3}, {%4,%5,%6,%7}, {%8,%9}, {%0,%1,%2,%3};"
        : "+f"(d[0]), "+f"(d[1]), "+f"(d[2]), "+f"(d[3])
        : "r"(a[0]), "r"(a[1]), "r"(a[2]), "r"(a[3]), "r"(b[0]), "r"(b[1]));
}
__device__ __forceinline__ void lds2u(uint32_t* r, uint32_t addr){
    asm volatile("ld.shared.v2.b32 {%0,%1}, [%2];" : "=r"(r[0]), "=r"(r[1]) : "r"(addr));
}
__device__ __forceinline__ void sts1u(uint32_t addr, uint32_t v){
    asm volatile("st.shared.b32 [%0], %1;" :: "r"(addr), "r"(v));
}

__global__ __launch_bounds__(NT, 1)
void deepfm_mma3(const int* __restrict__ X, const float* __restrict__ emb1,
                 const float* __restrict__ emb2,
                 const float* __restrict__ W1, const float* __restrict__ b1,
                 const float* __restrict__ g1, const float* __restrict__ be1,
                 const float* __restrict__ m1, const float* __restrict__ v1,
                 const float* __restrict__ W2, const float* __restrict__ b2,
                 const float* __restrict__ g2, const float* __restrict__ be2,
                 const float* __restrict__ m2, const float* __restrict__ v2,
                 const float* __restrict__ W3, const float* __restrict__ b3,
                 float* __restrict__ out, int Btot, int V)
{
    extern __shared__ float sm[];
    float* As      = sm + OFF_A;       // e2 [416][STRA]; later h1 [256][STRA]
    float* fm_s    = sm + OFF_FM;
    float* logit_s = sm + OFF_LOGIT;
    float* S1f     = sm + OFF_S1;
    float* B1f     = sm + OFF_B1;
    float* S2f     = sm + OFF_S2;
    float* B2f     = sm + OFF_B2;
    float* W3s     = sm + OFF_W3;

    const int tid  = threadIdx.x;
    const int wid  = tid >> 5;
    const int lane = tid & 31;
    const int b0   = blockIdx.x * ROWS;
    const uint32_t smbase = smem_u32(sm);

    if (tid < 64) { fm_s[tid] = 0.f; logit_s[tid] = 0.f; }
    if (tid < 256) {
        float s = g1[tid] * rsqrtf(v1[tid] + EPSF);
        S1f[tid] = s; B1f[tid] = be1[tid] + (b1[tid] - m1[tid]) * s;
        if (tid < 128) {
            float s2 = g2[tid] * rsqrtf(v2[tid] + EPSF);
            S2f[tid] = s2; B2f[tid] = be2[tid] + (b2[tid] - m2[tid]) * s2;
            W3s[tid] = W3[tid];
        }
    }
    __syncthreads();

    // ---- Phase 1: gather e2 -> plain [k][row] (fp32, conflict-free) + FM1 ----
    for (int p = tid; p < ROWS*NF; p += NT) {
        int r = p & (ROWS-1);
        int f = p >> 6;                 // 0..25
        int idx = X[(size_t)(b0 + r) * NF + f];
        atomicAdd(&fm_s[r], emb1[(size_t)f * V + idx]);
        const float4* e = (const float4*)(emb2 + ((size_t)f * V + idx) * ND);
        #pragma unroll
        for (int q = 0; q < 4; q++) {
            float4 v = e[q];
            As[(f*ND + 4*q + 0)*STRA + r] = v.x;
            As[(f*ND + 4*q + 1)*STRA + r] = v.y;
            As[(f*ND + 4*q + 2)*STRA + r] = v.z;
            As[(f*ND + 4*q + 3)*STRA + r] = v.w;
        }
    }
    __syncthreads();

    const float4* W1g = (const float4*)W1;   // [416][64 float4]
    const float4* W2g = (const float4*)W2;   // [256][32 float4]

    // ---- Phase 2: second-order FM (exact fp32) + stage W1 chunk 0 ----
    for (int p = tid; p < ROWS*ND; p += NT) {
        int r = p & (ROWS-1);
        int d = p >> 6;                 // 0..15
        float s = 0.f, sq = 0.f;
        #pragma unroll
        for (int f = 0; f < NF; f++) {
            float v = As[(f*ND + d)*STRA + r];
            s += v; sq += v*v;
        }
        atomicAdd(&fm_s[r], 0.5f*(s*s - sq));
    }
    {
        #pragma unroll
        for (int i = 0; i < 4; i++) {
            int t = tid + i*NT;                  // < 2048
            int kk = t >> 6, c4 = t & 63;        // kk: k-local 0..31, c4: float4 col
            float4 w = W1g[(size_t)kk * 64 + c4];
            float wv[4] = {w.x, w.y, w.z, w.w};
            int kcol = kk & 7;
            #pragma unroll
            for (int b = 0; b < 4; b++) {
                int n = c4*4 + b;
                uint32_t fr = (uint32_t)((kk >> 3)*32 + (n >> 3));
                uint32_t fl = fr*FRS + (uint32_t)(((n & 7)*4 + (kcol & 3))*2 + (kcol >> 2));
                sts1u(smbase + (OFF_WB0 + fl)*4u, f2tf(wv[b]));
            }
        }
    }
    __syncthreads();

    // ---- GEMM1: 13 chunks of 32k (4 k-steps), warp = m16 x n64 ----
    const int wm = wid & 3, wn = wid >> 2;
    const int g  = lane >> 2, t4 = lane & 3;
    const int r0 = wm*16 + g;
    float acc[32];
    #pragma unroll
    for (int i = 0; i < 32; i++) acc[i] = 0.f;
    {
        float4 pf[4];
        #pragma unroll 1
        for (int c = 0; c < 13; c++) {
            if (c + 1 < 13) {
                #pragma unroll
                for (int i = 0; i < 4; i++) {
                    int t = tid + i*NT;
                    pf[i] = W1g[(size_t)((c+1)*32 + (t >> 6)) * 64 + (t & 63)];
                }
            }
            uint32_t bufb = smbase + (uint32_t)((c & 1) ? OFF_WB1 : OFF_WB0)*4u;
            #pragma unroll
            for (int ks = 0; ks < 4; ks++) {
                const float* ak = As + (size_t)((c*4 + ks)*8 + t4)*STRA;
                uint32_t a[4];
                a[0] = f2tf(ak[r0]);
                a[1] = f2tf(ak[r0 + 8]);
                a[2] = f2tf(ak[4*STRA + r0]);
                a[3] = f2tf(ak[4*STRA + r0 + 8]);
                #pragma unroll
                for (int nf = 0; nf < 8; nf++) {
                    uint32_t b[2];
                    lds2u(b, bufb + ((uint32_t)(ks*32 + wn*8 + nf)*FRS + (uint32_t)lane*2u)*4u);
                    mma_tf32(&acc[nf*4], a, b);
                }
            }
            if (c + 1 < 13) {
                uint32_t dstb = smbase + (uint32_t)((c & 1) ? OFF_WB0 : OFF_WB1)*4u;
                #pragma unroll
                for (int i = 0; i < 4; i++) {
                    int t = tid + i*NT;
                    int kk = t >> 6, c4 = t & 63;
                    int kcol = kk & 7;
                    float wv[4] = {pf[i].x, pf[i].y, pf[i].z, pf[i].w};
                    #pragma unroll
                    for (int b = 0; b < 4; b++) {
                        int n = c4*4 + b;
                        uint32_t fr = (uint32_t)((kk >> 3)*32 + (n >> 3));
                        uint32_t fl = fr*FRS + (uint32_t)(((n & 7)*4 + (kcol & 3))*2 + (kcol >> 2));
                        sts1u(dstb + fl*4u, f2tf(wv[b]));
                    }
                }
            }
            __syncthreads();
        }
    }

    // ---- BN1 + ReLU -> h1 plain [256][STRA] (conflict-free) + stage W2 chunk 0 ----
    {
        float4 pf[4];
        #pragma unroll
        for (int i = 0; i < 4; i++) {
            int t = tid + i*NT;                  // < 2048
            pf[i] = W2g[(size_t)(t >> 5) * 32 + (t & 31)];
        }
        #pragma unroll
        for (int nf = 0; nf < 8; nf++) {
            int c0 = wn*64 + nf*8 + 2*(lane & 3);
            float Sa = S1f[c0],   Ba = B1f[c0];
            float Sb = S1f[c0+1], Bb = B1f[c0+1];
            As[(size_t)c0*STRA     + r0    ] = fmaxf(acc[nf*4+0]*Sa + Ba, 0.f);
            As[(size_t)(c0+1)*STRA + r0    ] = fmaxf(acc[nf*4+1]*Sb + Bb, 0.f);
            As[(size_t)c0*STRA     + r0 + 8] = fmaxf(acc[nf*4+2]*Sa + Ba, 0.f);
            As[(size_t)(c0+1)*STRA + r0 + 8] = fmaxf(acc[nf*4+3]*Sb + Bb, 0.f);
        }
        #pragma unroll
        for (int i = 0; i < 4; i++) {
            int t = tid + i*NT;
            int kk = t >> 5, c4 = t & 31;        // kk: k-local 0..63
            int kcol = kk & 7;
            float wv[4] = {pf[i].x, pf[i].y, pf[i].z, pf[i].w};
            #pragma unroll
            for (int b = 0; b < 4; b++) {
                int n = c4*4 + b;
                uint32_t fr = (uint32_t)((kk >> 3)*16 + (n >> 3));
                uint32_t fl = fr*FRS + (uint32_t)(((n & 7)*4 + (kcol & 3))*2 + (kcol >> 2));
                sts1u(smbase + (OFF_WB0 + fl)*4u, f2tf(wv[b]));
            }
        }
    }
    __syncthreads();

    // ---- GEMM2: 4 chunks of 64k (8 k-steps), warp = m16 x n32 ----
    float acc2[16];
    #pragma unroll
    for (int i = 0; i < 16; i++) acc2[i] = 0.f;
    {
        float4 pf[4];
        #pragma unroll 1
        for (int c = 0; c < 4; c++) {
            if (c + 1 < 4) {
                #pragma unroll
                for (int i = 0; i < 4; i++) {
                    int t = tid + i*NT;
                    pf[i] = W2g[(size_t)((c+1)*64 + (t >> 5)) * 32 + (t & 31)];
                }
            }
            uint32_t bufb = smbase + (uint32_t)((c & 1) ? OFF_WB1 : OFF_WB0)*4u;
            #pragma unroll
            for (int ks = 0; ks < 8; ks++) {
                const float* ak = As + (size_t)((c*8 + ks)*8 + t4)*STRA;
                uint32_t a[4];
                a[0] = f2tf(ak[r0]);
                a[1] = f2tf(ak[r0 + 8]);
                a[2] = f2tf(ak[4*STRA + r0]);
                a[3] = f2tf(ak[4*STRA + r0 + 8]);
                #pragma unroll
                for (int nf = 0; nf < 4; nf++) {
                    uint32_t b[2];
                    lds2u(b, bufb + ((uint32_t)(ks*16 + wn*4 + nf)*FRS + (uint32_t)lane*2u)*4u);
                    mma_tf32(&acc2[nf*4], a, b);
                }
            }
            if (c + 1 < 4) {
                uint32_t dstb = smbase + (uint32_t)((c & 1) ? OFF_WB0 : OFF_WB1)*4u;
                #pragma unroll
                for (int i = 0; i < 4; i++) {
                    int t = tid + i*NT;
                    int kk = t >> 5, c4 = t & 31;
                    int kcol = kk & 7;
                    float wv[4] = {pf[i].x, pf[i].y, pf[i].z, pf[i].w};
                    #pragma unroll
                    for (int b = 0; b < 4; b++) {
                        int n = c4*4 + b;
                        uint32_t fr = (uint32_t)((kk >> 3)*16 + (n >> 3));
                        uint32_t fl = fr*FRS + (uint32_t)(((n & 7)*4 + (kcol & 3))*2 + (kcol >> 2));
                        sts1u(dstb + fl*4u, f2tf(wv[b]));
                    }
                }
            }
            __syncthreads();
        }
    }

    // ---- BN2 + ReLU + W3 dot on D2 frags -> logits ----
    {
        float sum0 = 0.f, sum1 = 0.f;
        #pragma unroll
        for (int nf = 0; nf < 4; nf++) {
            int c0 = wn*32 + nf*8 + 2*(lane & 3);
            float Sa = S2f[c0],   Ba = B2f[c0],   wa = W3s[c0];
            float Sb = S2f[c0+1], Bb = B2f[c0+1], wb = W3s[c0+1];
            sum0 += fmaxf(acc2[nf*4+0]*Sa + Ba, 0.f)*wa + fmaxf(acc2[nf*4+1]*Sb + Bb, 0.f)*wb;
            sum1 += fmaxf(acc2[nf*4+2]*Sa + Ba, 0.f)*wa + fmaxf(acc2[nf*4+3]*Sb + Bb, 0.f)*wb;
        }
        atomicAdd(&logit_s[r0],     sum0);
        atomicAdd(&logit_s[r0 + 8], sum1);
    }
    __syncthreads();

    // ---- Epilogue ----
    if (tid < ROWS) {
        float x = logit_s[tid] + fm_s[tid] + b3[0];
        out[b0 + tid] = 1.f / (1.f + expf(-x));
    }
}

extern "C" void kernel_launch(void* const* d_in, const int* in_sizes, int n_in,
                              void* d_out, int out_size)
{
    const int*   X    = (const int*)  d_in[0];
    const float* emb1 = (const float*)d_in[1];
    const float* emb2 = (const float*)d_in[2];
    const float* W1   = (const float*)d_in[3];
    const float* b1   = (const float*)d_in[4];
    const float* g1   = (const float*)d_in[5];
    const float* be1  = (const float*)d_in[6];
    const float* m1   = (const float*)d_in[7];
    const float* v1   = (const float*)d_in[8];
    const float* W2   = (const float*)d_in[9];
    const float* b2   = (const float*)d_in[10];
    const float* g2   = (const float*)d_in[11];
    const float* be2  = (const float*)d_in[12];
    const float* m2   = (const float*)d_in[13];
    const float* v2   = (const float*)d_in[14];
    const float* W3   = (const float*)d_in[15];
    const float* b3   = (const float*)d_in[16];
    float* out = (float*)d_out;

    int B = in_sizes[0] / NF;
    int V = in_sizes[1] / NF;

    int smem = SMEM_FLOATS * (int)sizeof(float);   // 184832 B
    cudaFuncSetAttribute(deepfm_mma3, cudaFuncAttributeMaxDynamicSharedMemorySize, smem);
    deepfm_mma3<<<B/ROWS, NT, smem>>>(X, emb1, emb2, W1, b1, g1, be1, m1, v1,
                                      W2, b2, g2, be2, m2, v2, W3, b3,
                                      out, B, V);
}

// round 12
// speedup vs baseline: 4.8403x; 1.6742x over previous
#include <cuda_runtime.h>
#include <math.h>
#include <stdint.h>

#define NF 26
#define ND 16
#define H1 256
#define H2 128
#define ROWS 64
#define EPSF 1e-5f
#define NT 512

#define AS 424      // A1 row stride (bf16): 848B = 16B*53, mod128=80 (phase order 8)
#define HS 264      // h1 row stride (bf16): 528B, mod128=16 (order 8)
#define WS1 264     // W1 stage k-row stride (bf16): 528B
#define WS2 136     // W2 stage k-row stride (bf16): 272B, mod128=16

// byte offsets in dynamic smem
#define A_B      0u            // 64*848 = 54272 B ; h1 (64*528=33792) reuses this region
#define WB0_B    54272u        // 17408 B each (W2 chunk 64*272=17408; W1 chunk 32*528=16896)
#define WB1_B    71680u
#define AUX_B    89088u        // 1024 floats
#define SMEM_BYTES (89088u + 4096u)   // 93184

__device__ __forceinline__ uint32_t smem_u32(const void* p){
    uint32_t a;
    asm("{ .reg .u64 t; cvta.to.shared.u64 t, %1; cvt.u32.u64 %0, t; }" : "=r"(a) : "l"(p));
    return a;
}
__device__ __forceinline__ uint32_t bf2(float lo, float hi){
    uint32_t r; asm("cvt.rn.bf16x2.f32 %0, %1, %2;" : "=r"(r) : "f"(hi), "f"(lo)); return r;
}
__device__ __forceinline__ void mma_bf16(float* d, const uint32_t* a, const uint32_t* b){
    asm volatile("mma.sync.aligned.m16n8k16.row.col.f32.bf16.bf16.f32 "
        "{%0,%1,%2,%3}, {%4,%5,%6,%7}, {%8,%9}, {%0,%1,%2,%3};"
        : "+f"(d[0]), "+f"(d[1]), "+f"(d[2]), "+f"(d[3])
        : "r"(a[0]), "r"(a[1]), "r"(a[2]), "r"(a[3]), "r"(b[0]), "r"(b[1]));
}
__device__ __forceinline__ void ldm4(uint32_t* r, uint32_t addr){
    asm volatile("ldmatrix.sync.aligned.m8n8.x4.shared.b16 {%0,%1,%2,%3}, [%4];"
        : "=r"(r[0]), "=r"(r[1]), "=r"(r[2]), "=r"(r[3]) : "r"(addr));
}
__device__ __forceinline__ void ldm4t(uint32_t* r, uint32_t addr){
    asm volatile("ldmatrix.sync.aligned.m8n8.x4.trans.shared.b16 {%0,%1,%2,%3}, [%4];"
        : "=r"(r[0]), "=r"(r[1]), "=r"(r[2]), "=r"(r[3]) : "r"(addr));
}
__device__ __forceinline__ void sts4u(uint32_t addr, uint32_t a, uint32_t b, uint32_t c, uint32_t d){
    asm volatile("st.shared.v4.b32 [%0], {%1,%2,%3,%4};" :: "r"(addr), "r"(a), "r"(b), "r"(c), "r"(d));
}
__device__ __forceinline__ void sts2u(uint32_t addr, uint32_t a, uint32_t b){
    asm volatile("st.shared.v2.b32 [%0], {%1,%2};" :: "r"(addr), "r"(a), "r"(b));
}
__device__ __forceinline__ void sts1u(uint32_t addr, uint32_t v){
    asm volatile("st.shared.b32 [%0], %1;" :: "r"(addr), "r"(v));
}

__global__ __launch_bounds__(NT, 1)
void deepfm_bf16(const int* __restrict__ X, const float* __restrict__ emb1,
                 const float* __restrict__ emb2,
                 const float* __restrict__ W1, const float* __restrict__ b1,
                 const float* __restrict__ g1, const float* __restrict__ be1,
                 const float* __restrict__ m1, const float* __restrict__ v1,
                 const float* __restrict__ W2, const float* __restrict__ b2,
                 const float* __restrict__ g2, const float* __restrict__ be2,
                 const float* __restrict__ m2, const float* __restrict__ v2,
                 const float* __restrict__ W3, const float* __restrict__ b3,
                 float* __restrict__ out, int Btot, int V)
{
    extern __shared__ char smc[];
    float* auxf    = (float*)(smc + AUX_B);
    float* fm_s    = auxf;
    float* logit_s = auxf + 64;
    float* S1f     = auxf + 128;
    float* B1f     = auxf + 384;
    float* S2f     = auxf + 640;
    float* B2f     = auxf + 768;
    float* W3s     = auxf + 896;

    const int tid  = threadIdx.x;
    const int wid  = tid >> 5;
    const int lane = tid & 31;
    const int b0   = blockIdx.x * ROWS;
    const uint32_t smbase = smem_u32(smc);

    if (tid < 64) logit_s[tid] = 0.f;
    if (tid < 256) {
        float s = g1[tid] * rsqrtf(v1[tid] + EPSF);
        S1f[tid] = s; B1f[tid] = be1[tid] + (b1[tid] - m1[tid]) * s;
        if (tid < 128) {
            float s2 = g2[tid] * rsqrtf(v2[tid] + EPSF);
            S2f[tid] = s2; B2f[tid] = be2[tid] + (b2[tid] - m2[tid]) * s2;
            W3s[tid] = W3[tid];
        }
    }

    // ---- Phase 1: gather e2 -> A [row][k] bf16; FM exact fp32 in regs ----
    {
        const int gr = tid >> 3;        // 0..63
        const int fi = tid & 7;
        float s[ND], q[ND]; float fm1 = 0.f;
        #pragma unroll
        for (int d = 0; d < ND; d++) { s[d] = 0.f; q[d] = 0.f; }
        const int* xr = X + (size_t)(b0 + gr) * NF;
        #pragma unroll
        for (int j = 0; j < 4; j++) {
            int f = fi + 8*j;
            if (f < NF) {
                int idx = xr[f];
                fm1 += emb1[(size_t)f * V + idx];
                const float4* e = (const float4*)(emb2 + ((size_t)f * V + idx) * ND);
                float4 v0 = e[0], v1v = e[1], v2v = e[2], v3v = e[3];
                s[0]+=v0.x;  q[0]+=v0.x*v0.x;   s[1]+=v0.y;  q[1]+=v0.y*v0.y;
                s[2]+=v0.z;  q[2]+=v0.z*v0.z;   s[3]+=v0.w;  q[3]+=v0.w*v0.w;
                s[4]+=v1v.x; q[4]+=v1v.x*v1v.x; s[5]+=v1v.y; q[5]+=v1v.y*v1v.y;
                s[6]+=v1v.z; q[6]+=v1v.z*v1v.z; s[7]+=v1v.w; q[7]+=v1v.w*v1v.w;
                s[8]+=v2v.x; q[8]+=v2v.x*v2v.x; s[9]+=v2v.y; q[9]+=v2v.y*v2v.y;
                s[10]+=v2v.z;q[10]+=v2v.z*v2v.z;s[11]+=v2v.w;q[11]+=v2v.w*v2v.w;
                s[12]+=v3v.x;q[12]+=v3v.x*v3v.x;s[13]+=v3v.y;q[13]+=v3v.y*v3v.y;
                s[14]+=v3v.z;q[14]+=v3v.z*v3v.z;s[15]+=v3v.w;q[15]+=v3v.w*v3v.w;
                uint32_t ad = smbase + A_B + ((uint32_t)gr*AS + (uint32_t)f*16u)*2u;
                sts4u(ad,       bf2(v0.x, v0.y),  bf2(v0.z, v0.w),
                                bf2(v1v.x, v1v.y), bf2(v1v.z, v1v.w));
                sts4u(ad + 16u, bf2(v2v.x, v2v.y), bf2(v2v.z, v2v.w),
                                bf2(v3v.x, v3v.y), bf2(v3v.z, v3v.w));
            }
        }
        #pragma unroll
        for (int m = 1; m < 8; m <<= 1) {
            fm1 += __shfl_xor_sync(0xffffffffu, fm1, m);
            #pragma unroll
            for (int d = 0; d < ND; d++) {
                s[d] += __shfl_xor_sync(0xffffffffu, s[d], m);
                q[d] += __shfl_xor_sync(0xffffffffu, q[d], m);
            }
        }
        if (fi == 0) {
            float fm2 = 0.f;
            #pragma unroll
            for (int d = 0; d < ND; d++) fm2 += 0.5f*(s[d]*s[d] - q[d]);
            fm_s[gr] = fm1 + fm2;
        }
    }

    const float4* W1g = (const float4*)W1;   // [416][64 float4]
    const float4* W2g = (const float4*)W2;   // [256][32 float4]

    // ---- stage W1 chunk 0 (32 k-rows) into WB0 as [k][n] bf16 ----
    {
        #pragma unroll
        for (int i = 0; i < 4; i++) {
            int t = tid + i*NT;                 // < 2048
            int kk = t >> 6, c4 = t & 63;
            float4 w = W1g[(size_t)kk * 64 + c4];
            sts2u(smbase + WB0_B + ((uint32_t)kk*WS1 + (uint32_t)c4*4u)*2u,
                  bf2(w.x, w.y), bf2(w.z, w.w));
        }
    }
    __syncthreads();

    // ---- GEMM1: 13 chunks of 32k (2 k16-steps), warp = m16 x n64 ----
    const int wm = wid & 3, wn = wid >> 2;
    const int l15 = lane & 15, lhi = lane >> 4;
    const int g  = lane >> 2, t4 = lane & 3;
    const int r0 = wm*16 + g;
    float acc[32];
    #pragma unroll
    for (int i = 0; i < 32; i++) acc[i] = 0.f;
    {
        const uint32_t a_lane = smbase + A_B
            + (uint32_t)(wm*16 + l15)*(AS*2u) + (uint32_t)(lhi*8)*2u;
        float4 pf[4];
        #pragma unroll 1
        for (int c = 0; c < 13; c++) {
            if (c + 1 < 13) {
                #pragma unroll
                for (int i = 0; i < 4; i++) {
                    int t = tid + i*NT;
                    pf[i] = W1g[(size_t)((c+1)*32 + (t >> 6)) * 64 + (t & 63)];
                }
            }
            uint32_t bufb = smbase + ((c & 1) ? WB1_B : WB0_B);
            #pragma unroll
            for (int ks = 0; ks < 2; ks++) {
                int ksg = c*2 + ks;
                uint32_t a[4];
                ldm4(a, a_lane + (uint32_t)(ksg*16)*2u);
                uint32_t brow = bufb + (uint32_t)(ks*16 + l15)*(WS1*2u);
                #pragma unroll
                for (int p = 0; p < 4; p++) {
                    uint32_t b[4];
                    int nb = wn*8 + 2*p + lhi;
                    ldm4t(b, brow + (uint32_t)(nb*8)*2u);
                    mma_bf16(&acc[(2*p)*4],   a, b);
                    mma_bf16(&acc[(2*p+1)*4], a, b + 2);
                }
            }
            if (c + 1 < 13) {
                uint32_t dstb = smbase + ((c & 1) ? WB0_B : WB1_B);
                #pragma unroll
                for (int i = 0; i < 4; i++) {
                    int t = tid + i*NT;
                    int kk = t >> 6, c4 = t & 63;
                    sts2u(dstb + ((uint32_t)kk*WS1 + (uint32_t)c4*4u)*2u,
                          bf2(pf[i].x, pf[i].y), bf2(pf[i].z, pf[i].w));
                }
            }
            __syncthreads();
        }
    }

    // ---- BN1 + ReLU -> h1 [64][HS] bf16 (reuses A region) + stage W2 chunk 0 ----
    {
        float4 pf[4];
        #pragma unroll
        for (int i = 0; i < 4; i++) {
            int t = tid + i*NT;                 // < 2048
            pf[i] = W2g[(size_t)(t >> 5) * 32 + (t & 31)];
        }
        #pragma unroll
        for (int nf = 0; nf < 8; nf++) {
            int c0 = wn*64 + nf*8 + 2*t4;
            float Sa = S1f[c0],   Ba = B1f[c0];
            float Sb = S1f[c0+1], Bb = B1f[c0+1];
            float h00 = fmaxf(acc[nf*4+0]*Sa + Ba, 0.f);
            float h01 = fmaxf(acc[nf*4+1]*Sb + Bb, 0.f);
            float h10 = fmaxf(acc[nf*4+2]*Sa + Ba, 0.f);
            float h11 = fmaxf(acc[nf*4+3]*Sb + Bb, 0.f);
            uint32_t ad = smbase + A_B + ((uint32_t)r0*HS + (uint32_t)c0)*2u;
            sts1u(ad,             bf2(h00, h01));
            sts1u(ad + 8u*HS*2u,  bf2(h10, h11));
        }
        #pragma unroll
        for (int i = 0; i < 4; i++) {
            int t = tid + i*NT;
            int kk = t >> 5, c4 = t & 31;
            sts2u(smbase + WB0_B + ((uint32_t)kk*WS2 + (uint32_t)c4*4u)*2u,
                  bf2(pf[i].x, pf[i].y), bf2(pf[i].z, pf[i].w));
        }
    }
    __syncthreads();

    // ---- GEMM2: 4 chunks of 64k (4 k16-steps), warp = m16 x n32 ----
    float acc2[16];
    #pragma unroll
    for (int i = 0; i < 16; i++) acc2[i] = 0.f;
    {
        const uint32_t a_lane2 = smbase + A_B
            + (uint32_t)(wm*16 + l15)*(HS*2u) + (uint32_t)(lhi*8)*2u;
        float4 pf[4];
        #pragma unroll 1
        for (int c = 0; c < 4; c++) {
            if (c + 1 < 4) {
                #pragma unroll
                for (int i = 0; i < 4; i++) {
                    int t = tid + i*NT;
                    pf[i] = W2g[(size_t)((c+1)*64 + (t >> 5)) * 32 + (t & 31)];
                }
            }
            uint32_t bufb = smbase + ((c & 1) ? WB1_B : WB0_B);
            #pragma unroll
            for (int ks = 0; ks < 4; ks++) {
                int ksg = c*4 + ks;
                uint32_t a[4];
                ldm4(a, a_lane2 + (uint32_t)(ksg*16)*2u);
                uint32_t brow = bufb + (uint32_t)(ks*16 + l15)*(WS2*2u);
                #pragma unroll
                for (int p = 0; p < 2; p++) {
                    uint32_t b[4];
                    int nb = wn*4 + 2*p + lhi;
                    ldm4t(b, brow + (uint32_t)(nb*8)*2u);
                    mma_bf16(&acc2[(2*p)*4],   a, b);
                    mma_bf16(&acc2[(2*p+1)*4], a, b + 2);
                }
            }
            if (c + 1 < 4) {
                uint32_t dstb = smbase + ((c & 1) ? WB0_B : WB1_B);
                #pragma unroll
                for (int i = 0; i < 4; i++) {
                    int t = tid + i*NT;
                    int kk = t >> 5, c4 = t & 31;
                    sts2u(dstb + ((uint32_t)kk*WS2 + (uint32_t)c4*4u)*2u,
                          bf2(pf[i].x, pf[i].y), bf2(pf[i].z, pf[i].w));
                }
            }
            __syncthreads();
        }
    }

    // ---- BN2 + ReLU + W3 dot on D2 frags -> logits ----
    {
        float sum0 = 0.f, sum1 = 0.f;
        #pragma unroll
        for (int nf = 0; nf < 4; nf++) {
            int c0 = wn*32 + nf*8 + 2*t4;
            float Sa = S2f[c0],   Ba = B2f[c0],   wa = W3s[c0];
            float Sb = S2f[c0+1], Bb = B2f[c0+1], wb = W3s[c0+1];
            sum0 += fmaxf(acc2[nf*4+0]*Sa + Ba, 0.f)*wa + fmaxf(acc2[nf*4+1]*Sb + Bb, 0.f)*wb;
            sum1 += fmaxf(acc2[nf*4+2]*Sa + Ba, 0.f)*wa + fmaxf(acc2[nf*4+3]*Sb + Bb, 0.f)*wb;
        }
        atomicAdd(&logit_s[r0],     sum0);
        atomicAdd(&logit_s[r0 + 8], sum1);
    }
    __syncthreads();

    // ---- Epilogue ----
    if (tid < ROWS) {
        float x = logit_s[tid] + fm_s[tid] + b3[0];
        out[b0 + tid] = 1.f / (1.f + expf(-x));
    }
}

extern "C" void kernel_launch(void* const* d_in, const int* in_sizes, int n_in,
                              void* d_out, int out_size)
{
    const int*   X    = (const int*)  d_in[0];
    const float* emb1 = (const float*)d_in[1];
    const float* emb2 = (const float*)d_in[2];
    const float* W1   = (const float*)d_in[3];
    const float* b1   = (const float*)d_in[4];
    const float* g1   = (const float*)d_in[5];
    const float* be1  = (const float*)d_in[6];
    const float* m1   = (const float*)d_in[7];
    const float* v1   = (const float*)d_in[8];
    const float* W2   = (const float*)d_in[9];
    const float* b2   = (const float*)d_in[10];
    const float* g2   = (const float*)d_in[11];
    const float* be2  = (const float*)d_in[12];
    const float* m2   = (const float*)d_in[13];
    const float* v2   = (const float*)d_in[14];
    const float* W3   = (const float*)d_in[15];
    const float* b3   = (const float*)d_in[16];
    float* out = (float*)d_out;

    int B = in_sizes[0] / NF;
    int V = in_sizes[1] / NF;

    cudaFuncSetAttribute(deepfm_bf16, cudaFuncAttributeMaxDynamicSharedMemorySize, SMEM_BYTES);
    deepfm_bf16<<<B/ROWS, NT, SMEM_BYTES>>>(X, emb1, emb2, W1, b1, g1, be1, m1, v1,
                                            W2, b2, g2, be2, m2, v2, W3, b3,
                                            out, B, V);
}

// round 13
// speedup vs baseline: 6.2548x; 1.2922x over previous
#include <cuda_runtime.h>
#include <math.h>
#include <stdint.h>

#define NF 26
#define ND 16
#define H1 256
#define H2 128
#define ROWS 64
#define EPSF 1e-5f
#define NT 256

#define AS 424      // A1 row stride (bf16): 848B, mod128=80 (order-8 phase spread)
#define HS 264      // h1 row stride (bf16): 528B
#define WS1 264     // W1 stage k-row stride (bf16): 528B
#define WS2 136     // W2 stage k-row stride (bf16): 272B

// byte offsets in dynamic smem
#define A_B      0u            // 64*848 = 54272 B ; h1 (64*528) reuses this region
#define WB0_B    54272u        // 17408 B each
#define WB1_B    71680u
#define AUX_B    89088u
#define SMEM_BYTES (89088u + 4096u)   // 93184 B; x2 CTAs = 186368 <= SM smem

#define W1CHUNK 16896u         // 32 k-rows * 528 B
#define W2CHUNK 17408u         // 64 k-rows * 272 B

__device__ __align__(16) uint32_t W1p[416*132];   // [k][264 bf16] pre-packed
__device__ __align__(16) uint32_t W2p[256*68];    // [k][136 bf16]

__device__ __forceinline__ uint32_t smem_u32(const void* p){
    uint32_t a;
    asm("{ .reg .u64 t; cvta.to.shared.u64 t, %1; cvt.u32.u64 %0, t; }" : "=r"(a) : "l"(p));
    return a;
}
__device__ __forceinline__ uint32_t bf2(float lo, float hi){
    uint32_t r; asm("cvt.rn.bf16x2.f32 %0, %1, %2;" : "=r"(r) : "f"(hi), "f"(lo)); return r;
}
__device__ __forceinline__ void mma_bf16(float* d, const uint32_t* a, const uint32_t* b){
    asm volatile("mma.sync.aligned.m16n8k16.row.col.f32.bf16.bf16.f32 "
        "{%0,%1,%2,%3}, {%4,%5,%6,%7}, {%8,%9}, {%0,%1,%2,%3};"
        : "+f"(d[0]), "+f"(d[1]), "+f"(d[2]), "+f"(d[3])
        : "r"(a[0]), "r"(a[1]), "r"(a[2]), "r"(a[3]), "r"(b[0]), "r"(b[1]));
}
__device__ __forceinline__ void ldm4(uint32_t* r, uint32_t addr){
    asm volatile("ldmatrix.sync.aligned.m8n8.x4.shared.b16 {%0,%1,%2,%3}, [%4];"
        : "=r"(r[0]), "=r"(r[1]), "=r"(r[2]), "=r"(r[3]) : "r"(addr));
}
__device__ __forceinline__ void ldm4t(uint32_t* r, uint32_t addr){
    asm volatile("ldmatrix.sync.aligned.m8n8.x4.trans.shared.b16 {%0,%1,%2,%3}, [%4];"
        : "=r"(r[0]), "=r"(r[1]), "=r"(r[2]), "=r"(r[3]) : "r"(addr));
}
__device__ __forceinline__ void sts4u(uint32_t addr, uint32_t a, uint32_t b, uint32_t c, uint32_t d){
    asm volatile("st.shared.v4.b32 [%0], {%1,%2,%3,%4};" :: "r"(addr), "r"(a), "r"(b), "r"(c), "r"(d));
}
__device__ __forceinline__ void sts1u(uint32_t addr, uint32_t v){
    asm volatile("st.shared.b32 [%0], %1;" :: "r"(addr), "r"(v));
}
__device__ __forceinline__ void cpa16(uint32_t saddr, const void* g){
    asm volatile("cp.async.cg.shared.global [%0], [%1], 16;" :: "r"(saddr), "l"(g));
}
#define CPA_COMMIT() asm volatile("cp.async.commit_group;" ::: "memory")
#define CPA_WAIT0()  asm volatile("cp.async.wait_group 0;" ::: "memory")

// ---- pack W1/W2 to bf16 chunk-image layouts ----
__global__ void pack_w(const float* __restrict__ W1, const float* __restrict__ W2){
    int t = blockIdx.x * blockDim.x + threadIdx.x;
    if (t < 416*128) {
        int k = t >> 7, np = t & 127;
        W1p[k*132 + np] = bf2(W1[k*256 + 2*np], W1[k*256 + 2*np + 1]);
    } else if (t < 416*128 + 256*64) {
        int t2 = t - 416*128;
        int k = t2 >> 6, np = t2 & 63;
        W2p[k*68 + np] = bf2(W2[k*128 + 2*np], W2[k*128 + 2*np + 1]);
    }
}

__global__ __launch_bounds__(NT, 2)
void deepfm_bf16o(const int* __restrict__ X, const float* __restrict__ emb1,
                  const float* __restrict__ emb2,
                  const float* __restrict__ b1g,
                  const float* __restrict__ g1, const float* __restrict__ be1,
                  const float* __restrict__ m1, const float* __restrict__ v1,
                  const float* __restrict__ b2g,
                  const float* __restrict__ g2, const float* __restrict__ be2,
                  const float* __restrict__ m2, const float* __restrict__ v2,
                  const float* __restrict__ W3, const float* __restrict__ b3,
                  float* __restrict__ out, int Btot, int V)
{
    extern __shared__ char smc[];
    float* auxf    = (float*)(smc + AUX_B);
    float* fm_s    = auxf;
    float* logit_s = auxf + 64;
    float* S1f     = auxf + 128;
    float* B1f     = auxf + 384;
    float* S2f     = auxf + 640;
    float* B2f     = auxf + 768;
    float* W3s     = auxf + 896;

    const int tid  = threadIdx.x;
    const int wid  = tid >> 5;
    const int lane = tid & 31;
    const int b0   = blockIdx.x * ROWS;
    const uint32_t smbase = smem_u32(smc);
    const char* W1pb = (const char*)W1p;
    const char* W2pb = (const char*)W2p;

    // ---- stage W1 chunk 0 ASAP (overlaps with gather) ----
    for (int t = tid; t < (int)(W1CHUNK/16); t += NT)
        cpa16(smbase + WB0_B + (uint32_t)t*16u, W1pb + t*16);
    CPA_COMMIT();

    if (tid < 64) logit_s[tid] = 0.f;
    if (tid < 256) {
        float s = g1[tid] * rsqrtf(v1[tid] + EPSF);
        S1f[tid] = s; B1f[tid] = be1[tid] + (b1g[tid] - m1[tid]) * s;
        if (tid < 128) {
            float s2 = g2[tid] * rsqrtf(v2[tid] + EPSF);
            S2f[tid] = s2; B2f[tid] = be2[tid] + (b2g[tid] - m2[tid]) * s2;
            W3s[tid] = W3[tid];
        }
    }

    // ---- Phase 1: gather e2 -> A [row][k] bf16; FM exact fp32 in regs ----
    {
        const int gr = tid >> 2;        // 0..63
        const int fi = tid & 3;
        float s[ND], q[ND]; float fm1 = 0.f;
        #pragma unroll
        for (int d = 0; d < ND; d++) { s[d] = 0.f; q[d] = 0.f; }
        const int* xr = X + (size_t)(b0 + gr) * NF;
        #pragma unroll
        for (int j = 0; j < 7; j++) {
            int f = fi + 4*j;
            if (f < NF) {
                int idx = xr[f];
                fm1 += emb1[(size_t)f * V + idx];
                const float4* e = (const float4*)(emb2 + ((size_t)f * V + idx) * ND);
                float4 v0 = e[0], v1v = e[1], v2v = e[2], v3v = e[3];
                s[0]+=v0.x;  q[0]+=v0.x*v0.x;   s[1]+=v0.y;  q[1]+=v0.y*v0.y;
                s[2]+=v0.z;  q[2]+=v0.z*v0.z;   s[3]+=v0.w;  q[3]+=v0.w*v0.w;
                s[4]+=v1v.x; q[4]+=v1v.x*v1v.x; s[5]+=v1v.y; q[5]+=v1v.y*v1v.y;
                s[6]+=v1v.z; q[6]+=v1v.z*v1v.z; s[7]+=v1v.w; q[7]+=v1v.w*v1v.w;
                s[8]+=v2v.x; q[8]+=v2v.x*v2v.x; s[9]+=v2v.y; q[9]+=v2v.y*v2v.y;
                s[10]+=v2v.z;q[10]+=v2v.z*v2v.z;s[11]+=v2v.w;q[11]+=v2v.w*v2v.w;
                s[12]+=v3v.x;q[12]+=v3v.x*v3v.x;s[13]+=v3v.y;q[13]+=v3v.y*v3v.y;
                s[14]+=v3v.z;q[14]+=v3v.z*v3v.z;s[15]+=v3v.w;q[15]+=v3v.w*v3v.w;
                uint32_t ad = smbase + A_B + ((uint32_t)gr*AS + (uint32_t)f*16u)*2u;
                sts4u(ad,       bf2(v0.x, v0.y),  bf2(v0.z, v0.w),
                                bf2(v1v.x, v1v.y), bf2(v1v.z, v1v.w));
                sts4u(ad + 16u, bf2(v2v.x, v2v.y), bf2(v2v.z, v2v.w),
                                bf2(v3v.x, v3v.y), bf2(v3v.z, v3v.w));
            }
        }
        #pragma unroll
        for (int m = 1; m < 4; m <<= 1) {
            fm1 += __shfl_xor_sync(0xffffffffu, fm1, m);
            #pragma unroll
            for (int d = 0; d < ND; d++) {
                s[d] += __shfl_xor_sync(0xffffffffu, s[d], m);
                q[d] += __shfl_xor_sync(0xffffffffu, q[d], m);
            }
        }
        if (fi == 0) {
            float fm2 = 0.f;
            #pragma unroll
            for (int d = 0; d < ND; d++) fm2 += 0.5f*(s[d]*s[d] - q[d]);
            fm_s[gr] = fm1 + fm2;
        }
    }
    CPA_WAIT0();
    __syncthreads();

    // ---- GEMM1: 13 chunks of 32k (2 k16-steps), 8 warps, warp = m16 x n128 ----
    const int wm = wid & 3, wn = wid >> 2;          // wn in {0,1}
    const int l15 = lane & 15, lhi = lane >> 4;
    const int g  = lane >> 2, t4 = lane & 3;
    const int r0 = wm*16 + g;
    float acc[64];
    #pragma unroll
    for (int i = 0; i < 64; i++) acc[i] = 0.f;
    {
        const uint32_t a_lane = smbase + A_B
            + (uint32_t)(wm*16 + l15)*(AS*2u) + (uint32_t)(lhi*8)*2u;
        #pragma unroll 1
        for (int c = 0; c < 13; c++) {
            if (c + 1 < 13) {
                uint32_t dstb = smbase + ((c & 1) ? WB0_B : WB1_B);
                const char* src = W1pb + (size_t)(c+1)*W1CHUNK;
                for (int t = tid; t < (int)(W1CHUNK/16); t += NT)
                    cpa16(dstb + (uint32_t)t*16u, src + t*16);
                CPA_COMMIT();
            }
            uint32_t bufb = smbase + ((c & 1) ? WB1_B : WB0_B);
            #pragma unroll
            for (int ks = 0; ks < 2; ks++) {
                int ksg = c*2 + ks;
                uint32_t a[4];
                ldm4(a, a_lane + (uint32_t)(ksg*16)*2u);
                uint32_t brow = bufb + (uint32_t)(ks*16 + l15)*(WS1*2u);
                #pragma unroll
                for (int p = 0; p < 8; p++) {
                    uint32_t b[4];
                    int nb = wn*16 + 2*p + lhi;
                    ldm4t(b, brow + (uint32_t)(nb*8)*2u);
                    mma_bf16(&acc[(2*p)*4],   a, b);
                    mma_bf16(&acc[(2*p+1)*4], a, b + 2);
                }
            }
            CPA_WAIT0();
            __syncthreads();
        }
    }

    // ---- BN1 + ReLU -> h1 [64][HS] bf16 + stage W2 chunk 0 ----
    {
        for (int t = tid; t < (int)(W2CHUNK/16); t += NT)
            cpa16(smbase + WB0_B + (uint32_t)t*16u, W2pb + t*16);
        CPA_COMMIT();
        #pragma unroll
        for (int nf = 0; nf < 16; nf++) {
            int c0 = wn*128 + nf*8 + 2*t4;
            float Sa = S1f[c0],   Ba = B1f[c0];
            float Sb = S1f[c0+1], Bb = B1f[c0+1];
            float h00 = fmaxf(acc[nf*4+0]*Sa + Ba, 0.f);
            float h01 = fmaxf(acc[nf*4+1]*Sb + Bb, 0.f);
            float h10 = fmaxf(acc[nf*4+2]*Sa + Ba, 0.f);
            float h11 = fmaxf(acc[nf*4+3]*Sb + Bb, 0.f);
            uint32_t ad = smbase + A_B + ((uint32_t)r0*HS + (uint32_t)c0)*2u;
            sts1u(ad,            bf2(h00, h01));
            sts1u(ad + 8u*HS*2u, bf2(h10, h11));
        }
        CPA_WAIT0();
    }
    __syncthreads();

    // ---- GEMM2: 4 chunks of 64k (4 k16-steps), warp = m16 x n64 ----
    float acc2[32];
    #pragma unroll
    for (int i = 0; i < 32; i++) acc2[i] = 0.f;
    {
        const uint32_t a_lane2 = smbase + A_B
            + (uint32_t)(wm*16 + l15)*(HS*2u) + (uint32_t)(lhi*8)*2u;
        #pragma unroll 1
        for (int c = 0; c < 4; c++) {
            if (c + 1 < 4) {
                uint32_t dstb = smbase + ((c & 1) ? WB0_B : WB1_B);
                const char* src = W2pb + (size_t)(c+1)*W2CHUNK;
                for (int t = tid; t < (int)(W2CHUNK/16); t += NT)
                    cpa16(dstb + (uint32_t)t*16u, src + t*16);
                CPA_COMMIT();
            }
            uint32_t bufb = smbase + ((c & 1) ? WB1_B : WB0_B);
            #pragma unroll
            for (int ks = 0; ks < 4; ks++) {
                int ksg = c*4 + ks;
                uint32_t a[4];
                ldm4(a, a_lane2 + (uint32_t)(ksg*16)*2u);
                uint32_t brow = bufb + (uint32_t)(ks*16 + l15)*(WS2*2u);
                #pragma unroll
                for (int p = 0; p < 4; p++) {
                    uint32_t b[4];
                    int nb = wn*8 + 2*p + lhi;
                    ldm4t(b, brow + (uint32_t)(nb*8)*2u);
                    mma_bf16(&acc2[(2*p)*4],   a, b);
                    mma_bf16(&acc2[(2*p+1)*4], a, b + 2);
                }
            }
            CPA_WAIT0();
            __syncthreads();
        }
    }

    // ---- BN2 + ReLU + W3 dot -> logits ----
    {
        float sum0 = 0.f, sum1 = 0.f;
        #pragma unroll
        for (int nf = 0; nf < 8; nf++) {
            int c0 = wn*64 + nf*8 + 2*t4;
            float Sa = S2f[c0],   Ba = B2f[c0],   wa = W3s[c0];
            float Sb = S2f[c0+1], Bb = B2f[c0+1], wb = W3s[c0+1];
            sum0 += fmaxf(acc2[nf*4+0]*Sa + Ba, 0.f)*wa + fmaxf(acc2[nf*4+1]*Sb + Bb, 0.f)*wb;
            sum1 += fmaxf(acc2[nf*4+2]*Sa + Ba, 0.f)*wa + fmaxf(acc2[nf*4+3]*Sb + Bb, 0.f)*wb;
        }
        atomicAdd(&logit_s[r0],     sum0);
        atomicAdd(&logit_s[r0 + 8], sum1);
    }
    __syncthreads();

    // ---- Epilogue ----
    if (tid < ROWS) {
        float x = logit_s[tid] + fm_s[tid] + b3[0];
        out[b0 + tid] = 1.f / (1.f + expf(-x));
    }
}

extern "C" void kernel_launch(void* const* d_in, const int* in_sizes, int n_in,
                              void* d_out, int out_size)
{
    const int*   X    = (const int*)  d_in[0];
    const float* emb1 = (const float*)d_in[1];
    const float* emb2 = (const float*)d_in[2];
    const float* W1   = (const float*)d_in[3];
    const float* b1   = (const float*)d_in[4];
    const float* g1   = (const float*)d_in[5];
    const float* be1  = (const float*)d_in[6];
    const float* m1   = (const float*)d_in[7];
    const float* v1   = (const float*)d_in[8];
    const float* W2   = (const float*)d_in[9];
    const float* b2   = (const float*)d_in[10];
    const float* g2   = (const float*)d_in[11];
    const float* be2  = (const float*)d_in[12];
    const float* m2   = (const float*)d_in[13];
    const float* v2   = (const float*)d_in[14];
    const float* W3   = (const float*)d_in[15];
    const float* b3   = (const float*)d_in[16];
    float* out = (float*)d_out;

    int B = in_sizes[0] / NF;
    int V = in_sizes[1] / NF;

    pack_w<<<(416*128 + 256*64 + 255)/256, 256>>>(W1, W2);
    cudaFuncSetAttribute(deepfm_bf16o, cudaFuncAttributeMaxDynamicSharedMemorySize, SMEM_BYTES);
    deepfm_bf16o<<<B/ROWS, NT, SMEM_BYTES>>>(X, emb1, emb2, b1, g1, be1, m1, v1,
                                             b2, g2, be2, m2, v2, W3, b3,
                                             out, B, V);
}

// round 14
// speedup vs baseline: 6.6174x; 1.0580x over previous
#include <cuda_runtime.h>
#include <math.h>
#include <stdint.h>

#define NF 26
#define ND 16
#define H1 256
#define H2 128
#define ROWS 64
#define EPSF 1e-5f
#define NT 256

#define AS 424      // A1 row stride (bf16): 848B, mod128=80 (order-8 phase spread)
#define HS 264      // h1 row stride (bf16): 528B
#define WS1 264     // W1 stage k-row stride (bf16): 528B
#define WS2 136     // W2 stage k-row stride (bf16): 272B

// byte offsets in dynamic smem
#define A_B      0u            // 64*848 = 54272 B ; h1 (64*528) reuses this region
#define WB0_B    54272u        // 17408 B each
#define WB1_B    71680u
#define AUX_B    89088u
#define SMEM_BYTES (89088u + 4096u)   // 93184 B; x2 CTAs = 186368 <= SM smem

#define W1CHUNK 16896u         // 32 k-rows * 528 B
#define W2CHUNK 17408u         // 64 k-rows * 272 B

__device__ __align__(16) uint32_t W1p[416*132];   // [k][264 bf16] pre-packed
__device__ __align__(16) uint32_t W2p[256*68];    // [k][136 bf16]

__device__ __forceinline__ uint32_t smem_u32(const void* p){
    uint32_t a;
    asm("{ .reg .u64 t; cvta.to.shared.u64 t, %1; cvt.u32.u64 %0, t; }" : "=r"(a) : "l"(p));
    return a;
}
__device__ __forceinline__ uint32_t bf2(float lo, float hi){
    uint32_t r; asm("cvt.rn.bf16x2.f32 %0, %1, %2;" : "=r"(r) : "f"(hi), "f"(lo)); return r;
}
__device__ __forceinline__ void mma_bf16(float* d, const uint32_t* a, const uint32_t* b){
    asm volatile("mma.sync.aligned.m16n8k16.row.col.f32.bf16.bf16.f32 "
        "{%0,%1,%2,%3}, {%4,%5,%6,%7}, {%8,%9}, {%0,%1,%2,%3};"
        : "+f"(d[0]), "+f"(d[1]), "+f"(d[2]), "+f"(d[3])
        : "r"(a[0]), "r"(a[1]), "r"(a[2]), "r"(a[3]), "r"(b[0]), "r"(b[1]));
}
__device__ __forceinline__ void ldm4(uint32_t* r, uint32_t addr){
    asm volatile("ldmatrix.sync.aligned.m8n8.x4.shared.b16 {%0,%1,%2,%3}, [%4];"
        : "=r"(r[0]), "=r"(r[1]), "=r"(r[2]), "=r"(r[3]) : "r"(addr));
}
__device__ __forceinline__ void ldm4t(uint32_t* r, uint32_t addr){
    asm volatile("ldmatrix.sync.aligned.m8n8.x4.trans.shared.b16 {%0,%1,%2,%3}, [%4];"
        : "=r"(r[0]), "=r"(r[1]), "=r"(r[2]), "=r"(r[3]) : "r"(addr));
}
__device__ __forceinline__ void sts4u(uint32_t addr, uint32_t a, uint32_t b, uint32_t c, uint32_t d){
    asm volatile("st.shared.v4.b32 [%0], {%1,%2,%3,%4};" :: "r"(addr), "r"(a), "r"(b), "r"(c), "r"(d));
}
__device__ __forceinline__ void sts1u(uint32_t addr, uint32_t v){
    asm volatile("st.shared.b32 [%0], %1;" :: "r"(addr), "r"(v));
}
__device__ __forceinline__ void cpa16(uint32_t saddr, const void* g){
    asm volatile("cp.async.cg.shared.global [%0], [%1], 16;" :: "r"(saddr), "l"(g));
}
#define CPA_COMMIT() asm volatile("cp.async.commit_group;" ::: "memory")
#define CPA_WAIT0()  asm volatile("cp.async.wait_group 0;" ::: "memory")

// ---- pack W1/W2 to bf16 chunk-image layouts ----
__global__ void pack_w(const float* __restrict__ W1, const float* __restrict__ W2){
    int t = blockIdx.x * blockDim.x + threadIdx.x;
    if (t < 416*128) {
        int k = t >> 7, np = t & 127;
        W1p[k*132 + np] = bf2(W1[k*256 + 2*np], W1[k*256 + 2*np + 1]);
    } else if (t < 416*128 + 256*64) {
        int t2 = t - 416*128;
        int k = t2 >> 6, np = t2 & 63;
        W2p[k*68 + np] = bf2(W2[k*128 + 2*np], W2[k*128 + 2*np + 1]);
    }
}

__global__ __launch_bounds__(NT, 2)
void deepfm_bf16p(const int* __restrict__ X, const float* __restrict__ emb1,
                  const float* __restrict__ emb2,
                  const float* __restrict__ b1g,
                  const float* __restrict__ g1, const float* __restrict__ be1,
                  const float* __restrict__ m1, const float* __restrict__ v1,
                  const float* __restrict__ b2g,
                  const float* __restrict__ g2, const float* __restrict__ be2,
                  const float* __restrict__ m2, const float* __restrict__ v2,
                  const float* __restrict__ W3, const float* __restrict__ b3,
                  float* __restrict__ out, int Btot, int V)
{
    extern __shared__ char smc[];
    float* auxf    = (float*)(smc + AUX_B);
    float* fm_s    = auxf;
    float* logit_s = auxf + 64;
    float* S1f     = auxf + 128;
    float* B1f     = auxf + 384;
    float* S2f     = auxf + 640;
    float* B2f     = auxf + 768;
    float* W3s     = auxf + 896;

    const int tid  = threadIdx.x;
    const int wid  = tid >> 5;
    const int lane = tid & 31;
    const int b0   = blockIdx.x * ROWS;
    const uint32_t smbase = smem_u32(smc);
    const char* W1pb = (const char*)W1p;
    const char* W2pb = (const char*)W2p;

    // ---- stage W1 chunk 0 ASAP (overlaps with gather) ----
    for (int t = tid; t < (int)(W1CHUNK/16); t += NT)
        cpa16(smbase + WB0_B + (uint32_t)t*16u, W1pb + t*16);
    CPA_COMMIT();

    if (tid < 64) logit_s[tid] = 0.f;
    if (tid < 256) {
        float s = g1[tid] * rsqrtf(v1[tid] + EPSF);
        S1f[tid] = s; B1f[tid] = be1[tid] + (b1g[tid] - m1[tid]) * s;
        if (tid < 128) {
            float s2 = g2[tid] * rsqrtf(v2[tid] + EPSF);
            S2f[tid] = s2; B2f[tid] = be2[tid] + (b2g[tid] - m2[tid]) * s2;
            W3s[tid] = W3[tid];
        }
    }

    // ---- Phase 1: gather e2 -> A [row][k] bf16; FM exact fp32 in regs ----
    {
        const int gr = tid >> 2;        // 0..63
        const int fi = tid & 3;
        float s[ND], q[ND]; float fm1 = 0.f;
        #pragma unroll
        for (int d = 0; d < ND; d++) { s[d] = 0.f; q[d] = 0.f; }
        const int* xr = X + (size_t)(b0 + gr) * NF;
        #pragma unroll
        for (int j = 0; j < 7; j++) {
            int f = fi + 4*j;
            if (f < NF) {
                int idx = xr[f];
                fm1 += emb1[(size_t)f * V + idx];
                const float4* e = (const float4*)(emb2 + ((size_t)f * V + idx) * ND);
                float4 v0 = e[0], v1v = e[1], v2v = e[2], v3v = e[3];
                s[0]+=v0.x;  q[0]+=v0.x*v0.x;   s[1]+=v0.y;  q[1]+=v0.y*v0.y;
                s[2]+=v0.z;  q[2]+=v0.z*v0.z;   s[3]+=v0.w;  q[3]+=v0.w*v0.w;
                s[4]+=v1v.x; q[4]+=v1v.x*v1v.x; s[5]+=v1v.y; q[5]+=v1v.y*v1v.y;
                s[6]+=v1v.z; q[6]+=v1v.z*v1v.z; s[7]+=v1v.w; q[7]+=v1v.w*v1v.w;
                s[8]+=v2v.x; q[8]+=v2v.x*v2v.x; s[9]+=v2v.y; q[9]+=v2v.y*v2v.y;
                s[10]+=v2v.z;q[10]+=v2v.z*v2v.z;s[11]+=v2v.w;q[11]+=v2v.w*v2v.w;
                s[12]+=v3v.x;q[12]+=v3v.x*v3v.x;s[13]+=v3v.y;q[13]+=v3v.y*v3v.y;
                s[14]+=v3v.z;q[14]+=v3v.z*v3v.z;s[15]+=v3v.w;q[15]+=v3v.w*v3v.w;
                uint32_t ad = smbase + A_B + ((uint32_t)gr*AS + (uint32_t)f*16u)*2u;
                sts4u(ad,       bf2(v0.x, v0.y),  bf2(v0.z, v0.w),
                                bf2(v1v.x, v1v.y), bf2(v1v.z, v1v.w));
                sts4u(ad + 16u, bf2(v2v.x, v2v.y), bf2(v2v.z, v2v.w),
                                bf2(v3v.x, v3v.y), bf2(v3v.z, v3v.w));
            }
        }
        #pragma unroll
        for (int m = 1; m < 4; m <<= 1) {
            fm1 += __shfl_xor_sync(0xffffffffu, fm1, m);
            #pragma unroll
            for (int d = 0; d < ND; d++) {
                s[d] += __shfl_xor_sync(0xffffffffu, s[d], m);
                q[d] += __shfl_xor_sync(0xffffffffu, q[d], m);
            }
        }
        if (fi == 0) {
            float fm2 = 0.f;
            #pragma unroll
            for (int d = 0; d < ND; d++) fm2 += 0.5f*(s[d]*s[d] - q[d]);
            fm_s[gr] = fm1 + fm2;
        }
    }
    CPA_WAIT0();
    __syncthreads();

    // ---- GEMM1: 13 chunks of 32k (2 k16-steps), warp = (2 x m16) x n64 ----
    const int wm = wid & 1, wn = wid >> 1;          // wn in 0..3
    const int l15 = lane & 15, lhi = lane >> 4;
    const int g  = lane >> 2, t4 = lane & 3;
    float acc[64];                                   // [mt][nf][4]: mt<2, nf<8
    #pragma unroll
    for (int i = 0; i < 64; i++) acc[i] = 0.f;
    {
        const uint32_t aln0 = smbase + A_B
            + (uint32_t)(wm*32 + l15)*(AS*2u) + (uint32_t)(lhi*8)*2u;
        const uint32_t aln1 = aln0 + 16u*(AS*2u);
        #pragma unroll 1
        for (int c = 0; c < 13; c++) {
            if (c + 1 < 13) {
                uint32_t dstb = smbase + ((c & 1) ? WB0_B : WB1_B);
                const char* src = W1pb + (size_t)(c+1)*W1CHUNK;
                for (int t = tid; t < (int)(W1CHUNK/16); t += NT)
                    cpa16(dstb + (uint32_t)t*16u, src + t*16);
                CPA_COMMIT();
            }
            uint32_t bufb = smbase + ((c & 1) ? WB1_B : WB0_B);
            #pragma unroll
            for (int ks = 0; ks < 2; ks++) {
                int ksg = c*2 + ks;
                uint32_t a0[4], a1[4];
                ldm4(a0, aln0 + (uint32_t)(ksg*16)*2u);
                ldm4(a1, aln1 + (uint32_t)(ksg*16)*2u);
                uint32_t brow = bufb + (uint32_t)(ks*16 + l15)*(WS1*2u);
                #pragma unroll
                for (int p = 0; p < 4; p++) {
                    uint32_t b[4];
                    int nb = wn*8 + 2*p + lhi;
                    ldm4t(b, brow + (uint32_t)(nb*8)*2u);
                    mma_bf16(&acc[(2*p)*4],      a0, b);
                    mma_bf16(&acc[(2*p+1)*4],    a0, b + 2);
                    mma_bf16(&acc[32+(2*p)*4],   a1, b);
                    mma_bf16(&acc[32+(2*p+1)*4], a1, b + 2);
                }
            }
            CPA_WAIT0();
            __syncthreads();
        }
    }

    // ---- BN1 + ReLU -> h1 [64][HS] bf16 + stage W2 chunk 0 ----
    {
        for (int t = tid; t < (int)(W2CHUNK/16); t += NT)
            cpa16(smbase + WB0_B + (uint32_t)t*16u, W2pb + t*16);
        CPA_COMMIT();
        #pragma unroll
        for (int mt = 0; mt < 2; mt++) {
            int rb = wm*32 + mt*16 + g;
            #pragma unroll
            for (int nf = 0; nf < 8; nf++) {
                int c0 = wn*64 + nf*8 + 2*t4;
                int ix = mt*32 + nf*4;
                float Sa = S1f[c0],   Ba = B1f[c0];
                float Sb = S1f[c0+1], Bb = B1f[c0+1];
                float h00 = fmaxf(acc[ix+0]*Sa + Ba, 0.f);
                float h01 = fmaxf(acc[ix+1]*Sb + Bb, 0.f);
                float h10 = fmaxf(acc[ix+2]*Sa + Ba, 0.f);
                float h11 = fmaxf(acc[ix+3]*Sb + Bb, 0.f);
                uint32_t ad = smbase + A_B + ((uint32_t)rb*HS + (uint32_t)c0)*2u;
                sts1u(ad,            bf2(h00, h01));
                sts1u(ad + 8u*HS*2u, bf2(h10, h11));
            }
        }
        CPA_WAIT0();
    }
    __syncthreads();

    // ---- GEMM2: 4 chunks of 64k (4 k16-steps), warp = (2 x m16) x n32 ----
    float acc2[32];                                  // [mt][nf][4]: mt<2, nf<4
    #pragma unroll
    for (int i = 0; i < 32; i++) acc2[i] = 0.f;
    {
        const uint32_t aln0 = smbase + A_B
            + (uint32_t)(wm*32 + l15)*(HS*2u) + (uint32_t)(lhi*8)*2u;
        const uint32_t aln1 = aln0 + 16u*(HS*2u);
        #pragma unroll 1
        for (int c = 0; c < 4; c++) {
            if (c + 1 < 4) {
                uint32_t dstb = smbase + ((c & 1) ? WB0_B : WB1_B);
                const char* src = W2pb + (size_t)(c+1)*W2CHUNK;
                for (int t = tid; t < (int)(W2CHUNK/16); t += NT)
                    cpa16(dstb + (uint32_t)t*16u, src + t*16);
                CPA_COMMIT();
            }
            uint32_t bufb = smbase + ((c & 1) ? WB1_B : WB0_B);
            #pragma unroll
            for (int ks = 0; ks < 4; ks++) {
                int ksg = c*4 + ks;
                uint32_t a0[4], a1[4];
                ldm4(a0, aln0 + (uint32_t)(ksg*16)*2u);
                ldm4(a1, aln1 + (uint32_t)(ksg*16)*2u);
                uint32_t brow = bufb + (uint32_t)(ks*16 + l15)*(WS2*2u);
                #pragma unroll
                for (int p = 0; p < 2; p++) {
                    uint32_t b[4];
                    int nb = wn*4 + 2*p + lhi;
                    ldm4t(b, brow + (uint32_t)(nb*8)*2u);
                    mma_bf16(&acc2[(2*p)*4],      a0, b);
                    mma_bf16(&acc2[(2*p+1)*4],    a0, b + 2);
                    mma_bf16(&acc2[16+(2*p)*4],   a1, b);
                    mma_bf16(&acc2[16+(2*p+1)*4], a1, b + 2);
                }
            }
            CPA_WAIT0();
            __syncthreads();
        }
    }

    // ---- BN2 + ReLU + W3 dot -> logits ----
    {
        #pragma unroll
        for (int mt = 0; mt < 2; mt++) {
            int rb = wm*32 + mt*16 + g;
            float sum0 = 0.f, sum1 = 0.f;
            #pragma unroll
            for (int nf = 0; nf < 4; nf++) {
                int c0 = wn*32 + nf*8 + 2*t4;
                int ix = mt*16 + nf*4;
                float Sa = S2f[c0],   Ba = B2f[c0],   wa = W3s[c0];
                float Sb = S2f[c0+1], Bb = B2f[c0+1], wb = W3s[c0+1];
                sum0 += fmaxf(acc2[ix+0]*Sa + Ba, 0.f)*wa + fmaxf(acc2[ix+1]*Sb + Bb, 0.f)*wb;
                sum1 += fmaxf(acc2[ix+2]*Sa + Ba, 0.f)*wa + fmaxf(acc2[ix+3]*Sb + Bb, 0.f)*wb;
            }
            atomicAdd(&logit_s[rb],     sum0);
            atomicAdd(&logit_s[rb + 8], sum1);
        }
    }
    __syncthreads();

    // ---- Epilogue ----
    if (tid < ROWS) {
        float x = logit_s[tid] + fm_s[tid] + b3[0];
        out[b0 + tid] = 1.f / (1.f + expf(-x));
    }
}

extern "C" void kernel_launch(void* const* d_in, const int* in_sizes, int n_in,
                              void* d_out, int out_size)
{
    const int*   X    = (const int*)  d_in[0];
    const float* emb1 = (const float*)d_in[1];
    const float* emb2 = (const float*)d_in[2];
    const float* W1   = (const float*)d_in[3];
    const float* b1   = (const float*)d_in[4];
    const float* g1   = (const float*)d_in[5];
    const float* be1  = (const float*)d_in[6];
    const float* m1   = (const float*)d_in[7];
    const float* v1   = (const float*)d_in[8];
    const float* W2   = (const float*)d_in[9];
    const float* b2   = (const float*)d_in[10];
    const float* g2   = (const float*)d_in[11];
    const float* be2  = (const float*)d_in[12];
    const float* m2   = (const float*)d_in[13];
    const float* v2   = (const float*)d_in[14];
    const float* W3   = (const float*)d_in[15];
    const float* b3   = (const float*)d_in[16];
    float* out = (float*)d_out;

    int B = in_sizes[0] / NF;
    int V = in_sizes[1] / NF;

    pack_w<<<(416*128 + 256*64 + 255)/256, 256>>>(W1, W2);
    cudaFuncSetAttribute(deepfm_bf16p, cudaFuncAttributeMaxDynamicSharedMemorySize, SMEM_BYTES);
    deepfm_bf16p<<<B/ROWS, NT, SMEM_BYTES>>>(X, emb1, emb2, b1, g1, be1, m1, v1,
                                             b2, g2, be2, m2, v2, W3, b3,
                                             out, B, V);
}